// round 3
// baseline (speedup 1.0000x reference)
#include <cuda_runtime.h>
#include <cuda_bf16.h>

// ---------------- scratch (device globals; no allocation allowed) ----------------
__device__ float g_h1[4096 * 32 * 196];   // conv1 out (relu)  98MB
__device__ float g_h2[4096 * 64 * 49];    // conv2 out (relu)  49MB
__device__ float g_d1[4096 * 32 * 196];   // deconv1 out (relu) 98MB
__device__ int   g_idx[4096 * 49];        // VQ indices
__device__ float g_table[512 * 64];       // codebook @ dw0 + db0
__device__ float g_cbsq[512];             // ||codebook_c||^2 (XLA-order)
__device__ float g_vqpart[1568];          // per-block vq partial sums

// XLA GPU row-reduce order guess: p[i] individually rounded products,
// partial a[i] = p[i] + p[i+32], then binary tree 16,8,4,2,1.
__device__ __forceinline__ float xla_sumsq64(const float* v, int stride) {
    float p[64];
    #pragma unroll
    for (int k = 0; k < 64; k++) p[k] = __fmul_rn(v[k * stride], v[k * stride]);
    float a[32];
    #pragma unroll
    for (int i = 0; i < 32; i++) a[i] = __fadd_rn(p[i], p[i + 32]);
    #pragma unroll
    for (int s = 16; s > 0; s >>= 1)
        #pragma unroll
        for (int i = 0; i < 16; i++)
            if (i < s) a[i] = __fadd_rn(a[i], a[i + s]);
    return a[0];
}

// ---------------- K0: decode table + codebook norms ----------------
__global__ void k_prep(const float* __restrict__ cb, const float* __restrict__ dw0,
                       const float* __restrict__ db0) {
    int t = threadIdx.x;
    if (blockIdx.x < 128) {
        int id = blockIdx.x * 256 + t;      // 0..32767
        int c = id >> 6, o = id & 63;
        float s = db0[o];
        const float* cr = cb + c * 64;
        #pragma unroll 8
        for (int i = 0; i < 64; i++) s += cr[i] * dw0[i * 64 + o];
        g_table[id] = s;
    } else {
        for (int c = t; c < 512; c += 256) {
            g_cbsq[c] = xla_sumsq64(cb + c * 64, 1);
        }
    }
}

// ---------------- K1: conv1 4x4 s2 p1, 1->32, relu ----------------
__global__ void __launch_bounds__(256) k_conv1(const float* __restrict__ x,
                                               const float* __restrict__ w1,
                                               const float* __restrict__ b1) {
    __shared__ float xs[900];   // 30x30 zero-padded image
    __shared__ float ws[512];
    int b = blockIdx.x, t = threadIdx.x;
    for (int l = t; l < 900; l += 256) xs[l] = 0.f;
    for (int l = t; l < 512; l += 256) ws[l] = w1[l];
    __syncthreads();
    for (int l = t; l < 784; l += 256) {
        int iy = l / 28, ix = l % 28;
        xs[(iy + 1) * 30 + ix + 1] = x[b * 784 + l];
    }
    __syncthreads();
    if (t < 196) {
        int oy = t / 14, ox = t % 14;
        float acc[32];
        #pragma unroll
        for (int c = 0; c < 32; c++) acc[c] = b1[c];
        const float4* ws4 = (const float4*)ws;
        #pragma unroll
        for (int ky = 0; ky < 4; ky++)
        #pragma unroll
        for (int kx = 0; kx < 4; kx++) {
            float v = xs[(2 * oy + ky) * 30 + 2 * ox + kx];
            int tb = (ky * 4 + kx) * 8;
            #pragma unroll
            for (int u = 0; u < 8; u++) {
                float4 w4 = ws4[tb + u];
                acc[4 * u + 0] += v * w4.x; acc[4 * u + 1] += v * w4.y;
                acc[4 * u + 2] += v * w4.z; acc[4 * u + 3] += v * w4.w;
            }
        }
        float* o = g_h1 + b * 6272 + t;
        #pragma unroll
        for (int c = 0; c < 32; c++) o[c * 196] = fmaxf(acc[c], 0.f);
    }
}

// ---------------- K2: conv2 4x4 s2 p1, 32->64, relu (2 imgs/block) ----------------
__global__ void __launch_bounds__(224, 1) k_conv2(const float* __restrict__ w2,
                                                  const float* __restrict__ b2) {
    extern __shared__ float sm[];
    float* ws = sm;               // 32768 floats: [tap16][ci32][co64]
    float* insm = sm + 32768;     // 2 x 32 x 16 x 17 = 17408 floats, zero padded
    int t = threadIdx.x;
    int b0 = blockIdx.x * 2;
    for (int l = t; l < 32768; l += 224) ws[l] = w2[l];
    for (int l = t; l < 17408; l += 224) insm[l] = 0.f;
    __syncthreads();
    for (int l = t; l < 12544; l += 224) {
        int img = l / 6272, rem = l % 6272;
        int ci = rem / 196, pos = rem % 196;
        int iy = pos / 14, ix = pos % 14;
        insm[img * 8704 + ci * 272 + (iy + 1) * 17 + ix + 1] = g_h1[(b0 + img) * 6272 + rem];
    }
    __syncthreads();
    int img = t / 112, r = t % 112;
    int oy = r / 16, cog = r % 16, co0 = cog * 4;
    float acc[7][4];
    #pragma unroll
    for (int i = 0; i < 7; i++) {
        acc[i][0] = b2[co0]; acc[i][1] = b2[co0 + 1];
        acc[i][2] = b2[co0 + 2]; acc[i][3] = b2[co0 + 3];
    }
    const float* inb = insm + img * 8704;
    const float4* ws4 = (const float4*)ws;
    for (int tap = 0; tap < 16; tap++) {
        int ky = tap >> 2, kx = tap & 3;
        const float* inr = inb + (2 * oy + ky) * 17 + kx;
        int wb = tap * 512 + (co0 >> 2);
        #pragma unroll 8
        for (int ci = 0; ci < 32; ci++) {
            float4 w4 = ws4[wb + ci * 16];
            const float* ip = inr + ci * 272;
            #pragma unroll
            for (int ox = 0; ox < 7; ox++) {
                float v = ip[2 * ox];
                acc[ox][0] += v * w4.x; acc[ox][1] += v * w4.y;
                acc[ox][2] += v * w4.z; acc[ox][3] += v * w4.w;
            }
        }
    }
    float* ob = g_h2 + (b0 + img) * 3136 + co0 * 49 + oy * 7;
    #pragma unroll
    for (int ox = 0; ox < 7; ox++)
        #pragma unroll
        for (int k = 0; k < 4; k++)
            ob[k * 49 + ox] = fmaxf(acc[ox][k], 0.f);
}

// ---------------- K3: conv3 (1x1, 64->64) + VQ, fused ----------------
// smem word offsets
#define HS_OFF    0       // 8192  (A tile, reused as codebook chunk)
#define WSM_OFF   8192    // 4096
#define ZSM_OFF   12288   // 128*68 = 8704 (stride 68)
#define RS_OFF    20992   // 2048
#define RI_OFF    23040   // 2048 (ints)
#define CBSQ_OFF  25088   // 128
#define ROWB_OFF  25216   // 128 (ints)
#define ROWP_OFF  25344   // 128 (ints)
#define WIDX_OFF  25472   // 128 (ints)
#define SRED_OFF  25600   // 256
#define ZSQ_OFF   25856   // 128
#define K3_SMEM_WORDS 25984

__global__ void __launch_bounds__(256, 2) k_vq(const float* __restrict__ w3,
                                               const float* __restrict__ b3,
                                               const float* __restrict__ cb,
                                               float* __restrict__ out_z,
                                               float* __restrict__ out_zq,
                                               float* __restrict__ out_idx) {
    extern __shared__ float sm[];
    float* hs = sm + HS_OFF;
    float* wsm = sm + WSM_OFF;
    float* zsm = sm + ZSM_OFF;
    float* rs = sm + RS_OFF;
    int* ri = (int*)(sm + RI_OFF);
    float* cbsqs = sm + CBSQ_OFF;
    int* rowb = (int*)(sm + ROWB_OFF);
    int* rowp = (int*)(sm + ROWP_OFF);
    int* widx = (int*)(sm + WIDX_OFF);
    float* sred = sm + SRED_OFF;
    float* zsq_s = sm + ZSQ_OFF;

    int t = threadIdx.x;
    int m0 = blockIdx.x * 128;
    if (t < 128) { int m = m0 + t; rowb[t] = m / 49; rowp[t] = m % 49; }
    for (int l = t; l < 4096; l += 256) wsm[l] = w3[l];
    __syncthreads();
    for (int l = t; l < 8192; l += 256) {
        int r = l & 127, ci = l >> 7;
        hs[ci * 128 + r] = g_h2[rowb[r] * 3136 + ci * 49 + rowp[r]];
    }
    __syncthreads();
    // step 1: z = h2 @ w3 + b3  -> zsm (stride 68)
    {
        int rg = t >> 4, cg = t & 15;
        int r0 = rg * 8, co0 = cg * 4;
        float acc[8][4];
        float4 b4 = ((const float4*)b3)[cg];
        #pragma unroll
        for (int j = 0; j < 8; j++) {
            acc[j][0] = b4.x; acc[j][1] = b4.y; acc[j][2] = b4.z; acc[j][3] = b4.w;
        }
        const float4* wsm4 = (const float4*)wsm;
        #pragma unroll 4
        for (int ci = 0; ci < 64; ci++) {
            float4 w4 = wsm4[ci * 16 + cg];
            const float* hp = hs + ci * 128 + r0;
            #pragma unroll
            for (int j = 0; j < 8; j++) {
                float a = hp[j];
                acc[j][0] += a * w4.x; acc[j][1] += a * w4.y;
                acc[j][2] += a * w4.z; acc[j][3] += a * w4.w;
            }
        }
        #pragma unroll
        for (int j = 0; j < 8; j++) {
            float* zp = zsm + (r0 + j) * 68 + co0;
            zp[0] = acc[j][0]; zp[1] = acc[j][1]; zp[2] = acc[j][2]; zp[3] = acc[j][3];
        }
    }
    __syncthreads();
    // zsq per row in XLA order; coalesced z write
    if (t < 128) zsq_s[t] = xla_sumsq64(zsm + t * 68, 1);
    for (int l = t; l < 8192; l += 256) {
        int r = l & 127, co = l >> 7;
        out_z[rowb[r] * 3136 + co * 49 + rowp[r]] = zsm[r * 68 + co];
    }
    // step 2: argmin over codes of fl(fl(zsq+csq) - fl(2*dot)), first-index ties
    float bsv[8]; int bix[8];
    #pragma unroll
    for (int j = 0; j < 8; j++) { bsv[j] = 3.4e38f; bix[j] = 0; }
    int rg = t >> 4, cg2 = t & 15;
    int r0 = rg * 8, c0 = cg2 * 8;
    for (int cc = 0; cc < 4; cc++) {
        __syncthreads();
        for (int l = t; l < 8192; l += 256) hs[l] = cb[cc * 8192 + l];
        if (t < 128) cbsqs[t] = g_cbsq[cc * 128 + t];
        __syncthreads();
        float acc[8][8];
        #pragma unroll
        for (int jr = 0; jr < 8; jr++)
            #pragma unroll
            for (int jc = 0; jc < 8; jc++) acc[jr][jc] = 0.f;
        const float4* z4p = (const float4*)zsm;
        const float4* c4p = (const float4*)hs;
        // sequential-FMA dot over k=0..63 (k-outer keeps each acc chain in order)
        for (int d4 = 0; d4 < 16; d4++) {
            float4 zv[8];
            #pragma unroll
            for (int j = 0; j < 8; j++) zv[j] = z4p[(r0 + j) * 17 + d4];
            #pragma unroll
            for (int jc = 0; jc < 8; jc++) {
                float4 cv = c4p[(c0 + jc) * 16 + d4];
                #pragma unroll
                for (int jr = 0; jr < 8; jr++) {
                    float a = acc[jr][jc];
                    a = __fmaf_rn(zv[jr].x, cv.x, a);
                    a = __fmaf_rn(zv[jr].y, cv.y, a);
                    a = __fmaf_rn(zv[jr].z, cv.z, a);
                    a = __fmaf_rn(zv[jr].w, cv.w, a);
                    acc[jr][jc] = a;
                }
            }
        }
        #pragma unroll
        for (int jc = 0; jc < 8; jc++) {
            float qn = cbsqs[c0 + jc];
            int id = cc * 128 + c0 + jc;
            #pragma unroll
            for (int jr = 0; jr < 8; jr++) {
                float T = __fadd_rn(zsq_s[r0 + jr], qn);
                float m2 = __fmul_rn(2.0f, acc[jr][jc]);
                float d = __fadd_rn(T, -m2);
                if (d < bsv[jr]) { bsv[jr] = d; bix[jr] = id; }   // ids ascend per thread
            }
        }
    }
    #pragma unroll
    for (int j = 0; j < 8; j++) { rs[(r0 + j) * 16 + cg2] = bsv[j]; ri[(r0 + j) * 16 + cg2] = bix[j]; }
    __syncthreads();
    if (t < 128) {
        float best = rs[t * 16]; int bid = ri[t * 16];
        #pragma unroll
        for (int k = 1; k < 16; k++) {
            float s = rs[t * 16 + k]; int id = ri[t * 16 + k];
            if (s < best || (s == best && id < bid)) { best = s; bid = id; }
        }
        widx[t] = bid;
        int m = m0 + t;
        g_idx[m] = bid;
        out_idx[m] = (float)bid;
    }
    __syncthreads();
    // z_q straight-through write: fl(z + fl(q - z)); vq partial (fixed order)
    float psum = 0.f;
    for (int l = t; l < 8192; l += 256) {
        int r = l & 127, co = l >> 7;
        float q = cb[widx[r] * 64 + co];
        float zv = zsm[r * 68 + co];
        float st = __fadd_rn(zv, __fadd_rn(q, -zv));
        out_zq[rowb[r] * 3136 + co * 49 + rowp[r]] = st;
        float d = zv - q;
        psum += d * d;
    }
    sred[t] = psum;
    __syncthreads();
    for (int s = 128; s > 0; s >>= 1) {
        if (t < s) sred[t] += sred[t + s];
        __syncthreads();
    }
    if (t == 0) g_vqpart[blockIdx.x] = sred[0];
}

// ---------------- K3b: vq loss final reduce ----------------
__global__ void k_vqred(float* __restrict__ out_vq) {
    __shared__ float sred[256];
    int t = threadIdx.x;
    float s = 0.f;
    for (int l = t; l < 1568; l += 256) s += g_vqpart[l];
    sred[t] = s;
    __syncthreads();
    for (int k = 128; k > 0; k >>= 1) { if (t < k) sred[t] += sred[t + k]; __syncthreads(); }
    if (t == 0) out_vq[0] = sred[0] * 1.25f / (200704.f * 64.f);
}

// ---------------- K4: deconv1 4x4 up2 p2, 64->32, relu (gathers table[idx]) ----------------
__global__ void __launch_bounds__(224, 1) k_deconv1(const float* __restrict__ dw1,
                                                    const float* __restrict__ db1) {
    extern __shared__ float sm[];
    float* ws = sm;              // 32768: [tap16][ci64][co32]
    float* insm = sm + 32768;    // 64 x 9 x 10 = 5760, zero-padded
    int t = threadIdx.x, b = blockIdx.x;
    for (int l = t; l < 32768; l += 224) ws[l] = dw1[l];
    for (int l = t; l < 5760; l += 224) insm[l] = 0.f;
    __syncthreads();
    for (int l = t; l < 3136; l += 224) {
        int pos = l >> 6, d = l & 63;
        int i = pos / 7, j = pos % 7;
        insm[d * 90 + (i + 1) * 10 + j + 1] = g_table[g_idx[b * 49 + pos] * 64 + d];
    }
    __syncthreads();
    int par = t / 56, rem = t % 56;
    int q = rem / 8, cog = rem % 8, co0 = cog * 4;
    int ay = par >> 1, ax = par & 1;
    float acc[7][4];
    float4 bv = ((const float4*)db1)[cog];
    #pragma unroll
    for (int r = 0; r < 7; r++) {
        acc[r][0] = bv.x; acc[r][1] = bv.y; acc[r][2] = bv.z; acc[r][3] = bv.w;
    }
    const float4* ws4 = (const float4*)ws;
    #pragma unroll
    for (int dy = 0; dy < 2; dy++)
    #pragma unroll
    for (int dx = 0; dx < 2; dx++) {
        int ky = 2 * dy + ay, kx = 2 * dx + ax;
        const float* inr = insm + (q + dy + ay) * 10 + dx + ax;
        int wb = (ky * 4 + kx) * 512 + (co0 >> 2);
        #pragma unroll 8
        for (int ci = 0; ci < 64; ci++) {
            float4 w4 = ws4[wb + ci * 8];
            const float* ip = inr + ci * 90;
            #pragma unroll
            for (int r = 0; r < 7; r++) {
                float v = ip[r];
                acc[r][0] += v * w4.x; acc[r][1] += v * w4.y;
                acc[r][2] += v * w4.z; acc[r][3] += v * w4.w;
            }
        }
    }
    int oy = 2 * q + ay;
    float* ob = g_d1 + b * 6272 + co0 * 196 + oy * 14 + ax;
    #pragma unroll
    for (int r = 0; r < 7; r++)
        #pragma unroll
        for (int k = 0; k < 4; k++)
            ob[k * 196 + 2 * r] = fmaxf(acc[r][k], 0.f);
}

// ---------------- K5: deconv2 4x4 up2 p2, 32->1, sigmoid ----------------
__global__ void __launch_bounds__(224, 3) k_deconv2(const float* __restrict__ dw2,
                                                    const float* __restrict__ db2,
                                                    float* __restrict__ out_recon) {
    extern __shared__ float sm[];
    float* insm = sm;            // 2 x 32 x 16 x 17 = 17408
    float* ws = sm + 17408;      // 512
    int t = threadIdx.x, b0 = blockIdx.x * 2;
    for (int l = t; l < 512; l += 224) ws[l] = dw2[l];
    for (int l = t; l < 17408; l += 224) insm[l] = 0.f;
    __syncthreads();
    for (int l = t; l < 12544; l += 224) {
        int img = l / 6272, rem = l % 6272;
        int ci = rem / 196, pos = rem % 196;
        int iy = pos / 14, ix = pos % 14;
        insm[img * 8704 + ci * 272 + (iy + 1) * 17 + ix + 1] = g_d1[(b0 + img) * 6272 + rem];
    }
    __syncthreads();
    int img = t / 112, r2 = t % 112;
    int par = r2 / 28, rem2 = r2 % 28;
    int q = rem2 / 2, rh = rem2 % 2, r0c = rh * 7;
    int ay = par >> 1, ax = par & 1;
    float acc[7];
    float bv = db2[0];
    #pragma unroll
    for (int r = 0; r < 7; r++) acc[r] = bv;
    const float* inb = insm + img * 8704;
    #pragma unroll
    for (int dy = 0; dy < 2; dy++)
    #pragma unroll
    for (int dx = 0; dx < 2; dx++) {
        int ky = 2 * dy + ay, kx = 2 * dx + ax;
        const float* inr = inb + (q + dy + ay) * 17 + r0c + dx + ax;
        const float* wp = ws + (ky * 4 + kx) * 32;
        #pragma unroll 8
        for (int ci = 0; ci < 32; ci++) {
            float w = wp[ci];
            const float* ip = inr + ci * 272;
            #pragma unroll
            for (int r = 0; r < 7; r++) acc[r] += ip[r] * w;
        }
    }
    int oy = 2 * q + ay;
    float* ob = out_recon + (b0 + img) * 784 + oy * 28 + ax;
    #pragma unroll
    for (int r = 0; r < 7; r++) {
        float v = acc[r];
        ob[2 * (r0c + r)] = 1.f / (1.f + __expf(-v));
    }
}

// ---------------- launch ----------------
extern "C" void kernel_launch(void* const* d_in, const int* in_sizes, int n_in,
                              void* d_out, int out_size) {
    const float* x   = (const float*)d_in[0];
    const float* w1  = (const float*)d_in[1];
    const float* b1  = (const float*)d_in[2];
    const float* w2  = (const float*)d_in[3];
    const float* b2  = (const float*)d_in[4];
    const float* w3  = (const float*)d_in[5];
    const float* b3  = (const float*)d_in[6];
    const float* cb  = (const float*)d_in[7];
    const float* dw0 = (const float*)d_in[8];
    const float* db0 = (const float*)d_in[9];
    const float* dw1 = (const float*)d_in[10];
    const float* db1 = (const float*)d_in[11];
    const float* dw2 = (const float*)d_in[12];
    const float* db2 = (const float*)d_in[13];

    float* out = (float*)d_out;
    float* out_recon = out;                       // 4096*1*28*28 = 3,211,264
    float* out_z     = out_recon + 3211264;       // 4096*64*7*7  = 12,845,056
    float* out_zq    = out_z + 12845056;          // 12,845,056
    float* out_vq    = out_zq + 12845056;         // 1
    float* out_idx   = out_vq + 1;                // 4096*49 = 200,704

    cudaFuncSetAttribute(k_conv2,   cudaFuncAttributeMaxDynamicSharedMemorySize, 200704);
    cudaFuncSetAttribute(k_vq,      cudaFuncAttributeMaxDynamicSharedMemorySize, K3_SMEM_WORDS * 4);
    cudaFuncSetAttribute(k_deconv1, cudaFuncAttributeMaxDynamicSharedMemorySize, 154112);
    cudaFuncSetAttribute(k_deconv2, cudaFuncAttributeMaxDynamicSharedMemorySize, 71680);

    k_prep<<<129, 256>>>(cb, dw0, db0);
    k_conv1<<<4096, 256>>>(x, w1, b1);
    k_conv2<<<2048, 224, 200704>>>(w2, b2);
    k_vq<<<1568, 256, K3_SMEM_WORDS * 4>>>(w3, b3, cb, out_z, out_zq, out_idx);
    k_vqred<<<1, 256>>>(out_vq);
    k_deconv1<<<4096, 224, 154112>>>(dw1, db1);
    k_deconv2<<<2048, 224, 71680>>>(dw2, db2, out_recon);
}

// round 4
// speedup vs baseline: 1.7765x; 1.7765x over previous
#include <cuda_runtime.h>
#include <cuda_bf16.h>

// ---------------- scratch (device globals; no allocation allowed) ----------------
__device__ float g_h1[4096 * 32 * 196];   // conv1 out (relu), NHWC [b][pos14x14][ci32]
__device__ float g_h2[4096 * 64 * 49];    // conv2 out (relu), row-major [m=b*49+pos][co64]
__device__ float g_d1[4096 * 32 * 196];   // deconv1 out (relu), NCHW
__device__ int   g_idx[4096 * 49];        // VQ indices
__device__ float g_table[512 * 64];       // codebook @ dw0 + db0
__device__ float g_cbsq[512];             // ||codebook_c||^2 (XLA-order)
__device__ float g_vqpart[1568];          // per-block vq partial sums

// XLA GPU row-reduce order: products individually rounded, pairwise p[i]+p[i+32],
// then binary tree 16,8,4,2,1.  (Matched reference in round 3.)
__device__ __forceinline__ float xla_sumsq64(const float* v, int stride) {
    float p[64];
    #pragma unroll
    for (int k = 0; k < 64; k++) p[k] = __fmul_rn(v[k * stride], v[k * stride]);
    float a[32];
    #pragma unroll
    for (int i = 0; i < 32; i++) a[i] = __fadd_rn(p[i], p[i + 32]);
    #pragma unroll
    for (int s = 16; s > 0; s >>= 1)
        #pragma unroll
        for (int i = 0; i < 16; i++)
            if (i < s) a[i] = __fadd_rn(a[i], a[i + s]);
    return a[0];
}

// ---------------- K0: decode table + codebook norms ----------------
__global__ void k_prep(const float* __restrict__ cb, const float* __restrict__ dw0,
                       const float* __restrict__ db0) {
    int t = threadIdx.x;
    if (blockIdx.x < 128) {
        int id = blockIdx.x * 256 + t;      // 0..32767
        int c = id >> 6, o = id & 63;
        float s = db0[o];
        const float* cr = cb + c * 64;
        #pragma unroll 8
        for (int i = 0; i < 64; i++) s += cr[i] * dw0[i * 64 + o];
        g_table[id] = s;
    } else {
        for (int c = t; c < 512; c += 256) {
            g_cbsq[c] = xla_sumsq64(cb + c * 64, 1);
        }
    }
}

// ---------------- K1: conv1 4x4 s2 p1, 1->32, relu -> NHWC ----------------
__global__ void __launch_bounds__(256) k_conv1(const float* __restrict__ x,
                                               const float* __restrict__ w1,
                                               const float* __restrict__ b1) {
    __shared__ float xs[900];   // 30x30 zero-padded image
    __shared__ float ws[512];
    int b = blockIdx.x, t = threadIdx.x;
    for (int l = t; l < 900; l += 256) xs[l] = 0.f;
    for (int l = t; l < 512; l += 256) ws[l] = w1[l];
    __syncthreads();
    for (int l = t; l < 784; l += 256) {
        int iy = l / 28, ix = l % 28;
        xs[(iy + 1) * 30 + ix + 1] = x[b * 784 + l];
    }
    __syncthreads();
    if (t < 196) {
        int oy = t / 14, ox = t % 14;
        float acc[32];
        #pragma unroll
        for (int c = 0; c < 32; c++) acc[c] = b1[c];
        const float4* ws4 = (const float4*)ws;
        #pragma unroll
        for (int ky = 0; ky < 4; ky++)
        #pragma unroll
        for (int kx = 0; kx < 4; kx++) {
            float v = xs[(2 * oy + ky) * 30 + 2 * ox + kx];
            int tb = (ky * 4 + kx) * 8;
            #pragma unroll
            for (int u = 0; u < 8; u++) {
                float4 w4 = ws4[tb + u];
                acc[4 * u + 0] += v * w4.x; acc[4 * u + 1] += v * w4.y;
                acc[4 * u + 2] += v * w4.z; acc[4 * u + 3] += v * w4.w;
            }
        }
        // NHWC write: 32 contiguous floats per position
        float4* o = (float4*)(g_h1 + b * 6272 + t * 32);
        #pragma unroll
        for (int u = 0; u < 8; u++) {
            float4 v4;
            v4.x = fmaxf(acc[4 * u + 0], 0.f);
            v4.y = fmaxf(acc[4 * u + 1], 0.f);
            v4.z = fmaxf(acc[4 * u + 2], 0.f);
            v4.w = fmaxf(acc[4 * u + 3], 0.f);
            o[u] = v4;
        }
    }
}

// ---------------- K2: conv2 4x4 s2 p1, 32->64, relu (2 imgs/block) ----------------
// Weights stay in L2 (read via __ldg); smem holds only the input tiles.
#define C2_CI_STRIDE 273          // 16x17 padded image + 1 pad word (odd => conflict-free)
#define C2_IMG_WORDS (32 * C2_CI_STRIDE)   // 8736
#define C2_SMEM_WORDS (2 * C2_IMG_WORDS)   // 17472

__global__ void __launch_bounds__(224, 3) k_conv2(const float* __restrict__ w2,
                                                  const float* __restrict__ b2) {
    extern __shared__ float insm[];
    int t = threadIdx.x;
    int b0 = blockIdx.x * 2;
    for (int l = t; l < C2_SMEM_WORDS; l += 224) insm[l] = 0.f;
    __syncthreads();
    for (int l = t; l < 12544; l += 224) {
        int img = l / 6272, rem = l % 6272;
        int pos = rem >> 5, ci = rem & 31;
        int iy = pos / 14, ix = pos % 14;
        insm[img * C2_IMG_WORDS + ci * C2_CI_STRIDE + (iy + 1) * 17 + ix + 1] =
            g_h1[(b0 + img) * 6272 + pos * 32 + ci];
    }
    __syncthreads();
    int img = t / 112, r = t % 112;
    int oy = r / 16, cog = r % 16, co0 = cog * 4;
    float acc[7][4];
    #pragma unroll
    for (int i = 0; i < 7; i++) {
        acc[i][0] = b2[co0]; acc[i][1] = b2[co0 + 1];
        acc[i][2] = b2[co0 + 2]; acc[i][3] = b2[co0 + 3];
    }
    const float* inb = insm + img * C2_IMG_WORDS;
    const float4* w24 = (const float4*)w2;
    for (int tap = 0; tap < 16; tap++) {
        int ky = tap >> 2, kx = tap & 3;
        const float* inr = inb + (2 * oy + ky) * 17 + kx;
        int wb = tap * 512 + cog;          // float4 index: (tap*32+ci)*16 + cog
        #pragma unroll 8
        for (int ci = 0; ci < 32; ci++) {
            float4 w4 = __ldg(&w24[wb + ci * 16]);
            const float* ip = inr + ci * C2_CI_STRIDE;
            #pragma unroll
            for (int ox = 0; ox < 7; ox++) {
                float v = ip[2 * ox];
                acc[ox][0] += v * w4.x; acc[ox][1] += v * w4.y;
                acc[ox][2] += v * w4.z; acc[ox][3] += v * w4.w;
            }
        }
    }
    // row-major write: g_h2[m][co], m = b*49 + oy*7 + ox
    float* ob = g_h2 + ((size_t)(b0 + img) * 49 + oy * 7) * 64 + co0;
    #pragma unroll
    for (int ox = 0; ox < 7; ox++) {
        float4 v4;
        v4.x = fmaxf(acc[ox][0], 0.f); v4.y = fmaxf(acc[ox][1], 0.f);
        v4.z = fmaxf(acc[ox][2], 0.f); v4.w = fmaxf(acc[ox][3], 0.f);
        *(float4*)(ob + ox * 64) = v4;
    }
}

// ---------------- K3: conv3 (1x1, 64->64) + VQ, fused ----------------
// smem word offsets
#define HS_OFF    0       // 8704: A tile [r][68] (row-major); reused as swizzled cb chunk
#define WSM_OFF   8704    // 4096: w3; reused after GEMM1 as rs(2048)+ri(2048)
#define ZSM_OFF   12800   // 128*68 = 8704 (stride 68)
#define CBSQ_OFF  21504   // 128
#define ROWB_OFF  21632   // 128 (ints)
#define ROWP_OFF  21760   // 128 (ints)
#define WIDX_OFF  21888   // 128 (ints)
#define SRED_OFF  22016   // 256
#define ZSQ_OFF   22272   // 128
#define K3_SMEM_WORDS 22400

__global__ void __launch_bounds__(256, 2) k_vq(const float* __restrict__ w3,
                                               const float* __restrict__ b3,
                                               const float* __restrict__ cb,
                                               float* __restrict__ out_z,
                                               float* __restrict__ out_zq,
                                               float* __restrict__ out_idx) {
    extern __shared__ float sm[];
    float* hs = sm + HS_OFF;
    float* wsm = sm + WSM_OFF;
    float* zsm = sm + ZSM_OFF;
    float* rs = sm + WSM_OFF;                 // overlays wsm (dead after GEMM1)
    int* ri = (int*)(sm + WSM_OFF + 2048);
    float* cbsqs = sm + CBSQ_OFF;
    int* rowb = (int*)(sm + ROWB_OFF);
    int* rowp = (int*)(sm + ROWP_OFF);
    int* widx = (int*)(sm + WIDX_OFF);
    float* sred = sm + SRED_OFF;
    float* zsq_s = sm + ZSQ_OFF;

    int t = threadIdx.x;
    int m0 = blockIdx.x * 128;
    if (t < 128) { int m = m0 + t; rowb[t] = m / 49; rowp[t] = m % 49; }
    for (int l = t; l < 4096; l += 256) wsm[l] = w3[l];
    // stage A row-major [r][68] from row-major g_h2 (coalesced, conflict-free)
    for (int l = t; l < 8192; l += 256) {
        int r = l >> 6, ci = l & 63;
        hs[r * 68 + ci] = g_h2[(size_t)(m0 + r) * 64 + ci];
    }
    __syncthreads();
    // step 1: z = h2 @ w3 + b3  -> zsm (stride 68); same FMA chain order as r3
    {
        int rg = t >> 4, cg = t & 15;
        int r0 = rg * 8, co0 = cg * 4;
        float acc[8][4];
        float4 b4 = ((const float4*)b3)[cg];
        #pragma unroll
        for (int j = 0; j < 8; j++) {
            acc[j][0] = b4.x; acc[j][1] = b4.y; acc[j][2] = b4.z; acc[j][3] = b4.w;
        }
        const float4* wsm4 = (const float4*)wsm;
        #pragma unroll 4
        for (int ci = 0; ci < 64; ci++) {
            float4 w4 = wsm4[ci * 16 + cg];
            #pragma unroll
            for (int j = 0; j < 8; j++) {
                float a = hs[(r0 + j) * 68 + ci];
                acc[j][0] += a * w4.x; acc[j][1] += a * w4.y;
                acc[j][2] += a * w4.z; acc[j][3] += a * w4.w;
            }
        }
        #pragma unroll
        for (int j = 0; j < 8; j++) {
            float* zp = zsm + (r0 + j) * 68 + co0;
            zp[0] = acc[j][0]; zp[1] = acc[j][1]; zp[2] = acc[j][2]; zp[3] = acc[j][3];
        }
    }
    __syncthreads();
    // zsq per row in XLA order; coalesced NCHW z write
    if (t < 128) zsq_s[t] = xla_sumsq64(zsm + t * 68, 1);
    for (int l = t; l < 8192; l += 256) {
        int r = l & 127, co = l >> 7;
        out_z[rowb[r] * 3136 + co * 49 + rowp[r]] = zsm[r * 68 + co];
    }
    // step 2: argmin over codes of fl(fl(zsq+csq) - fl(2*dot)), first-index ties
    float bsv[8]; int bix[8];
    #pragma unroll
    for (int j = 0; j < 8; j++) { bsv[j] = 3.4e38f; bix[j] = 0; }
    int rg = t >> 4, cg2 = t & 15;
    int r0 = rg * 8, c0 = cg2 * 8;
    float4* cs4 = (float4*)hs;   // swizzled codebook chunk overlays hs
    for (int cc = 0; cc < 4; cc++) {
        __syncthreads();
        // stage 128 codes x 64 dims, XOR-swizzled: slot = c*16 + ((d4 + (c>>3)) & 15)
        {
            const float4* cb4 = (const float4*)(cb) + cc * 2048;
            for (int l = t; l < 2048; l += 256) {
                int c = l >> 4, d4 = l & 15;
                cs4[c * 16 + ((d4 + (c >> 3)) & 15)] = cb4[l];
            }
        }
        if (t < 128) cbsqs[t] = g_cbsq[cc * 128 + t];
        __syncthreads();
        float acc[8][8];
        #pragma unroll
        for (int jr = 0; jr < 8; jr++)
            #pragma unroll
            for (int jc = 0; jc < 8; jc++) acc[jr][jc] = 0.f;
        const float4* z4p = (const float4*)zsm;
        // sequential-FMA dot over k=0..63 (k-outer keeps each acc chain in order)
        for (int d4 = 0; d4 < 16; d4++) {
            float4 zv[8];
            #pragma unroll
            for (int j = 0; j < 8; j++) zv[j] = z4p[(r0 + j) * 17 + d4];
            #pragma unroll
            for (int jc = 0; jc < 8; jc++) {
                int c = c0 + jc;
                float4 cv = cs4[c * 16 + ((d4 + cg2) & 15)];  // c>>3 == cg2
                #pragma unroll
                for (int jr = 0; jr < 8; jr++) {
                    float a = acc[jr][jc];
                    a = __fmaf_rn(zv[jr].x, cv.x, a);
                    a = __fmaf_rn(zv[jr].y, cv.y, a);
                    a = __fmaf_rn(zv[jr].z, cv.z, a);
                    a = __fmaf_rn(zv[jr].w, cv.w, a);
                    acc[jr][jc] = a;
                }
            }
        }
        #pragma unroll
        for (int jc = 0; jc < 8; jc++) {
            float qn = cbsqs[c0 + jc];
            int id = cc * 128 + c0 + jc;
            #pragma unroll
            for (int jr = 0; jr < 8; jr++) {
                float T = __fadd_rn(zsq_s[r0 + jr], qn);
                float m2 = __fmul_rn(2.0f, acc[jr][jc]);
                float d = __fadd_rn(T, -m2);
                if (d < bsv[jr]) { bsv[jr] = d; bix[jr] = id; }   // ids ascend per thread
            }
        }
    }
    __syncthreads();   // wsm region reuse (rs/ri)
    #pragma unroll
    for (int j = 0; j < 8; j++) { rs[(r0 + j) * 16 + cg2] = bsv[j]; ri[(r0 + j) * 16 + cg2] = bix[j]; }
    __syncthreads();
    if (t < 128) {
        float best = rs[t * 16]; int bid = ri[t * 16];
        #pragma unroll
        for (int k = 1; k < 16; k++) {
            float s = rs[t * 16 + k]; int id = ri[t * 16 + k];
            if (s < best || (s == best && id < bid)) { best = s; bid = id; }
        }
        widx[t] = bid;
        int m = m0 + t;
        g_idx[m] = bid;
        out_idx[m] = (float)bid;
    }
    __syncthreads();
    // z_q straight-through write: fl(z + fl(q - z)); vq partial (fixed order)
    float psum = 0.f;
    for (int l = t; l < 8192; l += 256) {
        int r = l & 127, co = l >> 7;
        float q = cb[widx[r] * 64 + co];
        float zv = zsm[r * 68 + co];
        float st = __fadd_rn(zv, __fadd_rn(q, -zv));
        out_zq[rowb[r] * 3136 + co * 49 + rowp[r]] = st;
        float d = zv - q;
        psum += d * d;
    }
    sred[t] = psum;
    __syncthreads();
    for (int s = 128; s > 0; s >>= 1) {
        if (t < s) sred[t] += sred[t + s];
        __syncthreads();
    }
    if (t == 0) g_vqpart[blockIdx.x] = sred[0];
}

// ---------------- K3b: vq loss final reduce ----------------
__global__ void k_vqred(float* __restrict__ out_vq) {
    __shared__ float sred[256];
    int t = threadIdx.x;
    float s = 0.f;
    for (int l = t; l < 1568; l += 256) s += g_vqpart[l];
    sred[t] = s;
    __syncthreads();
    for (int k = 128; k > 0; k >>= 1) { if (t < k) sred[t] += sred[t + k]; __syncthreads(); }
    if (t == 0) out_vq[0] = sred[0] * 1.25f / (200704.f * 64.f);
}

// ---------------- K4: deconv1 4x4 up2 p2, 64->32, relu (gathers table[idx]) ----------------
// Weights from L2 via __ldg; smem = input tile only (static, ~23KB) -> high occupancy.
__global__ void __launch_bounds__(224, 4) k_deconv1(const float* __restrict__ dw1,
                                                    const float* __restrict__ db1) {
    __shared__ float insm[64 * 91];   // [d][9x10 padded, stride 91]
    __shared__ int sidx[49];
    int t = threadIdx.x, b = blockIdx.x;
    if (t < 49) sidx[t] = g_idx[b * 49 + t];
    for (int l = t; l < 64 * 91; l += 224) insm[l] = 0.f;
    __syncthreads();
    for (int l = t; l < 3136; l += 224) {
        int pos = l >> 6, d = l & 63;
        int i = pos / 7, j = pos % 7;
        insm[d * 91 + (i + 1) * 10 + j + 1] = g_table[sidx[pos] * 64 + d];
    }
    __syncthreads();
    int par = t / 56, rem = t % 56;
    int q = rem / 8, cog = rem % 8, co0 = cog * 4;
    int ay = par >> 1, ax = par & 1;
    float acc[7][4];
    float4 bv = ((const float4*)db1)[cog];
    #pragma unroll
    for (int r = 0; r < 7; r++) {
        acc[r][0] = bv.x; acc[r][1] = bv.y; acc[r][2] = bv.z; acc[r][3] = bv.w;
    }
    const float4* dw14 = (const float4*)dw1;
    #pragma unroll
    for (int dy = 0; dy < 2; dy++)
    #pragma unroll
    for (int dx = 0; dx < 2; dx++) {
        int ky = 2 * dy + ay, kx = 2 * dx + ax;
        const float* inr = insm + (q + dy + ay) * 10 + dx + ax;
        int wb = (ky * 4 + kx) * 512 + cog;   // float4 index: (tap*64+ci)*8 + cog
        #pragma unroll 8
        for (int ci = 0; ci < 64; ci++) {
            float4 w4 = __ldg(&dw14[wb + ci * 8]);
            const float* ip = inr + ci * 91;
            #pragma unroll
            for (int r = 0; r < 7; r++) {
                float v = ip[r];
                acc[r][0] += v * w4.x; acc[r][1] += v * w4.y;
                acc[r][2] += v * w4.z; acc[r][3] += v * w4.w;
            }
        }
    }
    int oy = 2 * q + ay;
    float* ob = g_d1 + b * 6272 + co0 * 196 + oy * 14 + ax;
    #pragma unroll
    for (int r = 0; r < 7; r++)
        #pragma unroll
        for (int k = 0; k < 4; k++)
            ob[k * 196 + 2 * r] = fmaxf(acc[r][k], 0.f);
}

// ---------------- K5: deconv2 4x4 up2 p2, 32->1, sigmoid ----------------
__global__ void __launch_bounds__(224, 3) k_deconv2(const float* __restrict__ dw2,
                                                    const float* __restrict__ db2,
                                                    float* __restrict__ out_recon) {
    extern __shared__ float sm[];
    float* insm = sm;            // 2 x 32 x 16 x 17 = 17408
    float* ws = sm + 17408;      // 512
    int t = threadIdx.x, b0 = blockIdx.x * 2;
    for (int l = t; l < 512; l += 224) ws[l] = dw2[l];
    for (int l = t; l < 17408; l += 224) insm[l] = 0.f;
    __syncthreads();
    for (int l = t; l < 12544; l += 224) {
        int img = l / 6272, rem = l % 6272;
        int ci = rem / 196, pos = rem % 196;
        int iy = pos / 14, ix = pos % 14;
        insm[img * 8704 + ci * 272 + (iy + 1) * 17 + ix + 1] = g_d1[(b0 + img) * 6272 + rem];
    }
    __syncthreads();
    int img = t / 112, r2 = t % 112;
    int par = r2 / 28, rem2 = r2 % 28;
    int q = rem2 / 2, rh = rem2 % 2, r0c = rh * 7;
    int ay = par >> 1, ax = par & 1;
    float acc[7];
    float bv = db2[0];
    #pragma unroll
    for (int r = 0; r < 7; r++) acc[r] = bv;
    const float* inb = insm + img * 8704;
    #pragma unroll
    for (int dy = 0; dy < 2; dy++)
    #pragma unroll
    for (int dx = 0; dx < 2; dx++) {
        int ky = 2 * dy + ay, kx = 2 * dx + ax;
        const float* inr = inb + (q + dy + ay) * 17 + r0c + dx + ax;
        const float* wp = ws + (ky * 4 + kx) * 32;
        #pragma unroll 8
        for (int ci = 0; ci < 32; ci++) {
            float w = wp[ci];
            const float* ip = inr + ci * 272;
            #pragma unroll
            for (int r = 0; r < 7; r++) acc[r] += ip[r] * w;
        }
    }
    int oy = 2 * q + ay;
    float* ob = out_recon + (b0 + img) * 784 + oy * 28 + ax;
    #pragma unroll
    for (int r = 0; r < 7; r++) {
        float v = acc[r];
        ob[2 * (r0c + r)] = 1.f / (1.f + __expf(-v));
    }
}

// ---------------- launch ----------------
extern "C" void kernel_launch(void* const* d_in, const int* in_sizes, int n_in,
                              void* d_out, int out_size) {
    const float* x   = (const float*)d_in[0];
    const float* w1  = (const float*)d_in[1];
    const float* b1  = (const float*)d_in[2];
    const float* w2  = (const float*)d_in[3];
    const float* b2  = (const float*)d_in[4];
    const float* w3  = (const float*)d_in[5];
    const float* b3  = (const float*)d_in[6];
    const float* cb  = (const float*)d_in[7];
    const float* dw0 = (const float*)d_in[8];
    const float* db0 = (const float*)d_in[9];
    const float* dw1 = (const float*)d_in[10];
    const float* db1 = (const float*)d_in[11];
    const float* dw2 = (const float*)d_in[12];
    const float* db2 = (const float*)d_in[13];

    float* out = (float*)d_out;
    float* out_recon = out;                       // 4096*1*28*28 = 3,211,264
    float* out_z     = out_recon + 3211264;       // 4096*64*7*7  = 12,845,056
    float* out_zq    = out_z + 12845056;          // 12,845,056
    float* out_vq    = out_zq + 12845056;         // 1
    float* out_idx   = out_vq + 1;                // 4096*49 = 200,704

    cudaFuncSetAttribute(k_conv2,   cudaFuncAttributeMaxDynamicSharedMemorySize, C2_SMEM_WORDS * 4);
    cudaFuncSetAttribute(k_vq,      cudaFuncAttributeMaxDynamicSharedMemorySize, K3_SMEM_WORDS * 4);
    cudaFuncSetAttribute(k_deconv2, cudaFuncAttributeMaxDynamicSharedMemorySize, 71680);

    k_prep<<<129, 256>>>(cb, dw0, db0);
    k_conv1<<<4096, 256>>>(x, w1, b1);
    k_conv2<<<2048, 224, C2_SMEM_WORDS * 4>>>(w2, b2);
    k_vq<<<1568, 256, K3_SMEM_WORDS * 4>>>(w3, b3, cb, out_z, out_zq, out_idx);
    k_vqred<<<1, 256>>>(out_vq);
    k_deconv1<<<4096, 224>>>(dw1, db1);
    k_deconv2<<<2048, 224, 71680>>>(dw2, db2, out_recon);
}

// round 5
// speedup vs baseline: 1.9509x; 1.0982x over previous
#include <cuda_runtime.h>
#include <cuda_bf16.h>

typedef unsigned long long ull;

// ---------------- packed f32x2 helpers (FFMA2) ----------------
__device__ __forceinline__ ull f2pack(float lo, float hi) {
    ull d; asm("mov.b64 %0, {%1, %2};" : "=l"(d) : "f"(lo), "f"(hi)); return d;
}
__device__ __forceinline__ ull f2dup(float s) { return f2pack(s, s); }
__device__ __forceinline__ void f2unpack(float& lo, float& hi, ull s) {
    asm("mov.b64 {%0, %1}, %2;" : "=f"(lo), "=f"(hi) : "l"(s));
}
__device__ __forceinline__ ull f2fma(ull a, ull b, ull c) {
    ull d; asm("fma.rn.f32x2 %0, %1, %2, %3;" : "=l"(d) : "l"(a), "l"(b), "l"(c)); return d;
}

// ---------------- scratch (device globals; no allocation allowed) ----------------
__device__ float g_h1[4096 * 32 * 196];   // conv1 out (relu), NHWC [b][pos14x14][ci32]
__device__ float g_h2[4096 * 64 * 49];    // conv2 out (relu), row-major [m][co64]
__device__ float g_d1[4096 * 32 * 196];   // deconv1 out (relu), NCHW
__device__ int   g_idx[4096 * 49];        // VQ indices
__device__ float g_table[512 * 64];       // codebook @ dw0 + db0
__device__ float g_cbsq[512];             // ||codebook_c||^2 (XLA-order)
__device__ float g_vqpart[1568];          // per-block vq partial sums

// XLA GPU row-reduce order (matched reference in round 3).
__device__ __forceinline__ float xla_sumsq64(const float* v, int stride) {
    float p[64];
    #pragma unroll
    for (int k = 0; k < 64; k++) p[k] = __fmul_rn(v[k * stride], v[k * stride]);
    float a[32];
    #pragma unroll
    for (int i = 0; i < 32; i++) a[i] = __fadd_rn(p[i], p[i + 32]);
    #pragma unroll
    for (int s = 16; s > 0; s >>= 1)
        #pragma unroll
        for (int i = 0; i < 16; i++)
            if (i < s) a[i] = __fadd_rn(a[i], a[i + s]);
    return a[0];
}

// ---------------- K0: decode table + codebook norms ----------------
__global__ void k_prep(const float* __restrict__ cb, const float* __restrict__ dw0,
                       const float* __restrict__ db0) {
    int t = threadIdx.x;
    if (blockIdx.x < 128) {
        int id = blockIdx.x * 256 + t;
        int c = id >> 6, o = id & 63;
        float s = db0[o];
        const float* cr = cb + c * 64;
        #pragma unroll 8
        for (int i = 0; i < 64; i++) s += cr[i] * dw0[i * 64 + o];
        g_table[id] = s;
    } else {
        for (int c = t; c < 512; c += 256) g_cbsq[c] = xla_sumsq64(cb + c * 64, 1);
    }
}

// ---------------- K1: conv1 4x4 s2 p1, 1->32, relu -> NHWC (FFMA2 co-pairs) ----------------
__global__ void __launch_bounds__(256) k_conv1(const float* __restrict__ x,
                                               const float* __restrict__ w1,
                                               const float* __restrict__ b1) {
    __shared__ float xs[900];
    __shared__ __align__(16) float ws[512];
    int b = blockIdx.x, t = threadIdx.x;
    for (int l = t; l < 900; l += 256) xs[l] = 0.f;
    for (int l = t; l < 512; l += 256) ws[l] = w1[l];
    __syncthreads();
    for (int l = t; l < 784; l += 256) {
        int iy = l / 28, ix = l % 28;
        xs[(iy + 1) * 30 + ix + 1] = x[b * 784 + l];
    }
    __syncthreads();
    if (t < 196) {
        int oy = t / 14, ox = t % 14;
        ull acc[16];
        const ulonglong2* b2p = (const ulonglong2*)b1;
        #pragma unroll
        for (int u = 0; u < 8; u++) {
            ulonglong2 bb = b2p[u];
            acc[2 * u] = bb.x; acc[2 * u + 1] = bb.y;
        }
        const ulonglong2* ws2 = (const ulonglong2*)ws;
        #pragma unroll
        for (int ky = 0; ky < 4; ky++)
        #pragma unroll
        for (int kx = 0; kx < 4; kx++) {
            float v = xs[(2 * oy + ky) * 30 + 2 * ox + kx];
            ull vp = f2dup(v);
            int tb = (ky * 4 + kx) * 8;
            #pragma unroll
            for (int u = 0; u < 8; u++) {
                ulonglong2 wv = ws2[tb + u];
                acc[2 * u] = f2fma(vp, wv.x, acc[2 * u]);
                acc[2 * u + 1] = f2fma(vp, wv.y, acc[2 * u + 1]);
            }
        }
        float4* o = (float4*)(g_h1 + b * 6272 + t * 32);
        #pragma unroll
        for (int u = 0; u < 8; u++) {
            float a0, a1, a2, a3;
            f2unpack(a0, a1, acc[2 * u]);
            f2unpack(a2, a3, acc[2 * u + 1]);
            float4 v4;
            v4.x = fmaxf(a0, 0.f); v4.y = fmaxf(a1, 0.f);
            v4.z = fmaxf(a2, 0.f); v4.w = fmaxf(a3, 0.f);
            o[u] = v4;
        }
    }
}

// ---------------- K2: conv2 4x4 s2 p1, 32->64, relu (img-pair FFMA2) ----------------
// smem: [ci32][pos 16x17][img2], ci pair-stride 546 words (mod32=2 -> conflict-free staging)
#define C2_CI_PAIR 546
#define C2_SMEM_WORDS (32 * C2_CI_PAIR)   // 17472 words = 69.9KB

__global__ void __launch_bounds__(112, 3) k_conv2(const float* __restrict__ w2,
                                                  const float* __restrict__ b2) {
    extern __shared__ __align__(16) float insm[];
    int t = threadIdx.x;
    int b0 = blockIdx.x * 2;
    for (int l = t; l < C2_SMEM_WORDS; l += 112) insm[l] = 0.f;
    __syncthreads();
    // stage both images interleaved; l = (pos, ci, img)
    for (int l = t; l < 12544; l += 112) {
        int img = l & 1, ci = (l >> 1) & 31, pos = l >> 6;
        int iy = pos / 14, ix = pos % 14;
        insm[ci * C2_CI_PAIR + ((iy + 1) * 17 + ix + 1) * 2 + img] =
            g_h1[(b0 + img) * 6272 + pos * 32 + ci];
    }
    __syncthreads();
    int oy = t / 16, cog = t % 16, co0 = cog * 4;
    ull acc[7][4];
    {
        float4 bf = ((const float4*)b2)[cog];
        ull bd0 = f2dup(bf.x), bd1 = f2dup(bf.y), bd2 = f2dup(bf.z), bd3 = f2dup(bf.w);
        #pragma unroll
        for (int i = 0; i < 7; i++) {
            acc[i][0] = bd0; acc[i][1] = bd1; acc[i][2] = bd2; acc[i][3] = bd3;
        }
    }
    const float4* w24 = (const float4*)w2;
    const ull* insm2 = (const ull*)insm;
    for (int tap = 0; tap < 16; tap++) {
        int ky = tap >> 2, kx = tap & 3;
        int base = (2 * oy + ky) * 17 + kx;
        int wb = tap * 512 + cog;
        #pragma unroll 8
        for (int ci = 0; ci < 32; ci++) {
            float4 w4 = __ldg(&w24[wb + ci * 16]);
            ull wd0 = f2dup(w4.x), wd1 = f2dup(w4.y), wd2 = f2dup(w4.z), wd3 = f2dup(w4.w);
            const ull* ip = insm2 + ci * 273 + base;
            #pragma unroll
            for (int ox = 0; ox < 7; ox++) {
                ull v = ip[2 * ox];
                acc[ox][0] = f2fma(v, wd0, acc[ox][0]);
                acc[ox][1] = f2fma(v, wd1, acc[ox][1]);
                acc[ox][2] = f2fma(v, wd2, acc[ox][2]);
                acc[ox][3] = f2fma(v, wd3, acc[ox][3]);
            }
        }
    }
    size_t mA = (size_t)b0 * 49 + oy * 7;
    #pragma unroll
    for (int ox = 0; ox < 7; ox++) {
        float4 vA, vB;
        float lo, hi;
        f2unpack(lo, hi, acc[ox][0]); vA.x = fmaxf(lo, 0.f); vB.x = fmaxf(hi, 0.f);
        f2unpack(lo, hi, acc[ox][1]); vA.y = fmaxf(lo, 0.f); vB.y = fmaxf(hi, 0.f);
        f2unpack(lo, hi, acc[ox][2]); vA.z = fmaxf(lo, 0.f); vB.z = fmaxf(hi, 0.f);
        f2unpack(lo, hi, acc[ox][3]); vA.w = fmaxf(lo, 0.f); vB.w = fmaxf(hi, 0.f);
        *(float4*)(g_h2 + (mA + ox) * 64 + co0) = vA;
        *(float4*)(g_h2 + (mA + 49 + ox) * 64 + co0) = vB;
    }
}

// ---------------- K3: conv3 (1x1, 64->64) + VQ, fused (FFMA2) ----------------
// smem word offsets
#define HS_OFF    0       // 8704: A tile [r][68] row-major; reused as swizzled cb chunk
#define WSM_OFF   8704    // 4096: w3; reused after GEMM1 as rs(2048)+ri(2048)
#define ZSM_OFF   12800   // z column-major [k64][r128] stride 130 = 8320 words
#define CBSQ_OFF  21120   // 128
#define ROWB_OFF  21248   // 128 (ints)
#define ROWP_OFF  21376   // 128 (ints)
#define WIDX_OFF  21504   // 128 (ints)
#define SRED_OFF  21632   // 256
#define ZSQ_OFF   21888   // 128
#define K3_SMEM_WORDS 22016

__global__ void __launch_bounds__(256, 2) k_vq(const float* __restrict__ w3,
                                               const float* __restrict__ b3,
                                               const float* __restrict__ cb,
                                               float* __restrict__ out_z,
                                               float* __restrict__ out_zq,
                                               float* __restrict__ out_idx) {
    extern __shared__ __align__(16) float sm[];
    float* hs = sm + HS_OFF;
    float* wsm = sm + WSM_OFF;
    float* zsm = sm + ZSM_OFF;          // col-major [k][r], stride 130
    float* rs = sm + WSM_OFF;           // overlays wsm (dead after GEMM1)
    int* ri = (int*)(sm + WSM_OFF + 2048);
    float* cbsqs = sm + CBSQ_OFF;
    int* rowb = (int*)(sm + ROWB_OFF);
    int* rowp = (int*)(sm + ROWP_OFF);
    int* widx = (int*)(sm + WIDX_OFF);
    float* sred = sm + SRED_OFF;
    float* zsq_s = sm + ZSQ_OFF;

    int t = threadIdx.x;
    int m0 = blockIdx.x * 128;
    if (t < 128) { int m = m0 + t; rowb[t] = m / 49; rowp[t] = m % 49; }
    for (int l = t; l < 4096; l += 256) wsm[l] = w3[l];
    for (int l = t; l < 8192; l += 256) {
        int r = l >> 6, ci = l & 63;
        hs[r * 68 + ci] = g_h2[(size_t)(m0 + r) * 64 + ci];
    }
    __syncthreads();
    // step 1: z = h2 @ w3 + b3 -> zsm col-major. FFMA2 over co-pairs (chains identical).
    {
        int rg = t >> 4, cg = t & 15;
        int r0 = rg * 8, co0 = cg * 4;
        ull acc[8][2];
        {
            ulonglong2 bb = ((const ulonglong2*)b3)[cg];
            #pragma unroll
            for (int j = 0; j < 8; j++) { acc[j][0] = bb.x; acc[j][1] = bb.y; }
        }
        const ulonglong2* wsm2 = (const ulonglong2*)wsm;
        #pragma unroll 4
        for (int ci = 0; ci < 64; ci++) {
            ulonglong2 wv = wsm2[ci * 16 + cg];
            #pragma unroll
            for (int j = 0; j < 8; j++) {
                ull ap = f2dup(hs[(r0 + j) * 68 + ci]);
                acc[j][0] = f2fma(ap, wv.x, acc[j][0]);
                acc[j][1] = f2fma(ap, wv.y, acc[j][1]);
            }
        }
        #pragma unroll
        for (int j = 0; j < 8; j++) {
            float z0, z1, z2, z3;
            f2unpack(z0, z1, acc[j][0]);
            f2unpack(z2, z3, acc[j][1]);
            int r = r0 + j;
            zsm[(co0 + 0) * 130 + r] = z0;
            zsm[(co0 + 1) * 130 + r] = z1;
            zsm[(co0 + 2) * 130 + r] = z2;
            zsm[(co0 + 3) * 130 + r] = z3;
        }
    }
    __syncthreads();
    // zsq per row (XLA order, stride 130); coalesced NCHW z write
    if (t < 128) zsq_s[t] = xla_sumsq64(zsm + t, 130);
    for (int l = t; l < 8192; l += 256) {
        int r = l & 127, co = l >> 7;
        out_z[rowb[r] * 3136 + co * 49 + rowp[r]] = zsm[co * 130 + r];
    }
    // step 2: argmin distance, FFMA2 over row-pairs; chains k-sequential (bit-identical)
    float bsv[8]; int bix[8];
    #pragma unroll
    for (int j = 0; j < 8; j++) { bsv[j] = 3.4e38f; bix[j] = 0; }
    int rg = t >> 4, cg2 = t & 15;
    int r0 = rg * 8, c0 = cg2 * 8;
    float4* cs4 = (float4*)hs;
    const float2* cs2 = (const float2*)hs;
    const ull* zz = (const ull*)zsm;
    for (int cc = 0; cc < 4; cc++) {
        __syncthreads();
        {
            const float4* cb4 = (const float4*)(cb) + cc * 2048;
            for (int l = t; l < 2048; l += 256) {
                int c = l >> 4, d4 = l & 15;
                cs4[c * 16 + ((d4 + (c >> 3)) & 15)] = cb4[l];
            }
        }
        if (t < 128) cbsqs[t] = g_cbsq[cc * 128 + t];
        __syncthreads();
        ull acc[4][8];
        #pragma unroll
        for (int p = 0; p < 4; p++)
            #pragma unroll
            for (int jc = 0; jc < 8; jc++) acc[p][jc] = 0ull;
        for (int d4 = 0; d4 < 16; d4++) {
            // half A: dims 4d4, 4d4+1
            ull zpa[2][4];
            #pragma unroll
            for (int kk = 0; kk < 2; kk++) {
                int base = (4 * d4 + kk) * 65 + rg * 4;
                #pragma unroll
                for (int p = 0; p < 4; p++) zpa[kk][p] = zz[base + p];
            }
            #pragma unroll
            for (int jc = 0; jc < 8; jc++) {
                float2 cv = cs2[((c0 + jc) * 16 + ((d4 + cg2) & 15)) * 2];
                ull cd0 = f2dup(cv.x), cd1 = f2dup(cv.y);
                #pragma unroll
                for (int p = 0; p < 4; p++) {
                    ull a = acc[p][jc];
                    a = f2fma(zpa[0][p], cd0, a);
                    a = f2fma(zpa[1][p], cd1, a);
                    acc[p][jc] = a;
                }
            }
            // half B: dims 4d4+2, 4d4+3
            #pragma unroll
            for (int kk = 0; kk < 2; kk++) {
                int base = (4 * d4 + 2 + kk) * 65 + rg * 4;
                #pragma unroll
                for (int p = 0; p < 4; p++) zpa[kk][p] = zz[base + p];
            }
            #pragma unroll
            for (int jc = 0; jc < 8; jc++) {
                float2 cv = cs2[((c0 + jc) * 16 + ((d4 + cg2) & 15)) * 2 + 1];
                ull cd2 = f2dup(cv.x), cd3 = f2dup(cv.y);
                #pragma unroll
                for (int p = 0; p < 4; p++) {
                    ull a = acc[p][jc];
                    a = f2fma(zpa[0][p], cd2, a);
                    a = f2fma(zpa[1][p], cd3, a);
                    acc[p][jc] = a;
                }
            }
        }
        #pragma unroll
        for (int jc = 0; jc < 8; jc++) {
            float qn = cbsqs[c0 + jc];
            int id = cc * 128 + c0 + jc;
            #pragma unroll
            for (int p = 0; p < 4; p++) {
                float d0, d1;
                f2unpack(d0, d1, acc[p][jc]);
                {
                    float T = __fadd_rn(zsq_s[r0 + 2 * p], qn);
                    float d = __fadd_rn(T, -__fmul_rn(2.0f, d0));
                    if (d < bsv[2 * p]) { bsv[2 * p] = d; bix[2 * p] = id; }
                }
                {
                    float T = __fadd_rn(zsq_s[r0 + 2 * p + 1], qn);
                    float d = __fadd_rn(T, -__fmul_rn(2.0f, d1));
                    if (d < bsv[2 * p + 1]) { bsv[2 * p + 1] = d; bix[2 * p + 1] = id; }
                }
            }
        }
    }
    __syncthreads();   // wsm region reuse (rs/ri)
    #pragma unroll
    for (int j = 0; j < 8; j++) { rs[(r0 + j) * 16 + cg2] = bsv[j]; ri[(r0 + j) * 16 + cg2] = bix[j]; }
    __syncthreads();
    if (t < 128) {
        float best = rs[t * 16]; int bid = ri[t * 16];
        #pragma unroll
        for (int k = 1; k < 16; k++) {
            float s = rs[t * 16 + k]; int id = ri[t * 16 + k];
            if (s < best || (s == best && id < bid)) { best = s; bid = id; }
        }
        widx[t] = bid;
        int m = m0 + t;
        g_idx[m] = bid;
        out_idx[m] = (float)bid;
    }
    __syncthreads();
    float psum = 0.f;
    for (int l = t; l < 8192; l += 256) {
        int r = l & 127, co = l >> 7;
        float q = cb[widx[r] * 64 + co];
        float zv = zsm[co * 130 + r];
        float st = __fadd_rn(zv, __fadd_rn(q, -zv));
        out_zq[rowb[r] * 3136 + co * 49 + rowp[r]] = st;
        float d = zv - q;
        psum += d * d;
    }
    sred[t] = psum;
    __syncthreads();
    for (int s = 128; s > 0; s >>= 1) {
        if (t < s) sred[t] += sred[t + s];
        __syncthreads();
    }
    if (t == 0) g_vqpart[blockIdx.x] = sred[0];
}

// ---------------- K3b: vq loss final reduce ----------------
__global__ void k_vqred(float* __restrict__ out_vq) {
    __shared__ float sred[256];
    int t = threadIdx.x;
    float s = 0.f;
    for (int l = t; l < 1568; l += 256) s += g_vqpart[l];
    sred[t] = s;
    __syncthreads();
    for (int k = 128; k > 0; k >>= 1) { if (t < k) sred[t] += sred[t + k]; __syncthreads(); }
    if (t == 0) out_vq[0] = sred[0] * 1.25f / (200704.f * 64.f);
}

// ---------------- K4: deconv1 4x4 up2 p2, 64->32, relu (img-pair FFMA2) ----------------
// smem: [d64][pos 9x10 stride 91][img2] = 11648 words (46.6KB static)
__global__ void __launch_bounds__(224, 3) k_deconv1(const float* __restrict__ dw1,
                                                    const float* __restrict__ db1) {
    __shared__ __align__(16) float insm[64 * 182];
    __shared__ int sidx[98];
    int t = threadIdx.x, b0 = blockIdx.x * 2;
    if (t < 98) sidx[t] = g_idx[b0 * 49 + t];
    for (int l = t; l < 64 * 182; l += 224) insm[l] = 0.f;
    __syncthreads();
    for (int l = t; l < 6272; l += 224) {
        int img = l & 1, rem = l >> 1;
        int pos = rem >> 6, d = rem & 63;
        int i = pos / 7, j = pos % 7;
        insm[d * 182 + ((i + 1) * 10 + j + 1) * 2 + img] = g_table[sidx[img * 49 + pos] * 64 + d];
    }
    __syncthreads();
    int par = t / 56, rem = t % 56;
    int q = rem / 8, cog = rem % 8, co0 = cog * 4;
    int ay = par >> 1, ax = par & 1;
    ull acc[7][4];
    {
        float4 bf = ((const float4*)db1)[cog];
        ull bd0 = f2dup(bf.x), bd1 = f2dup(bf.y), bd2 = f2dup(bf.z), bd3 = f2dup(bf.w);
        #pragma unroll
        for (int r = 0; r < 7; r++) {
            acc[r][0] = bd0; acc[r][1] = bd1; acc[r][2] = bd2; acc[r][3] = bd3;
        }
    }
    const float4* dw14 = (const float4*)dw1;
    const ull* insm2 = (const ull*)insm;
    #pragma unroll
    for (int dy = 0; dy < 2; dy++)
    #pragma unroll
    for (int dx = 0; dx < 2; dx++) {
        int ky = 2 * dy + ay, kx = 2 * dx + ax;
        int base = (q + dy + ay) * 10 + dx + ax;
        int wb = (ky * 4 + kx) * 512 + cog;
        #pragma unroll 8
        for (int ci = 0; ci < 64; ci++) {
            float4 w4 = __ldg(&dw14[wb + ci * 8]);
            ull wd0 = f2dup(w4.x), wd1 = f2dup(w4.y), wd2 = f2dup(w4.z), wd3 = f2dup(w4.w);
            const ull* ip = insm2 + ci * 91 + base;
            #pragma unroll
            for (int r = 0; r < 7; r++) {
                ull v = ip[r];
                acc[r][0] = f2fma(v, wd0, acc[r][0]);
                acc[r][1] = f2fma(v, wd1, acc[r][1]);
                acc[r][2] = f2fma(v, wd2, acc[r][2]);
                acc[r][3] = f2fma(v, wd3, acc[r][3]);
            }
        }
    }
    int oy = 2 * q + ay;
    float* obA = g_d1 + b0 * 6272 + co0 * 196 + oy * 14 + ax;
    float* obB = obA + 6272;
    #pragma unroll
    for (int r = 0; r < 7; r++)
        #pragma unroll
        for (int k = 0; k < 4; k++) {
            float lo, hi;
            f2unpack(lo, hi, acc[r][k]);
            obA[k * 196 + 2 * r] = fmaxf(lo, 0.f);
            obB[k * 196 + 2 * r] = fmaxf(hi, 0.f);
        }
}

// ---------------- K5: deconv2 4x4 up2 p2, 32->1, sigmoid ----------------
__global__ void __launch_bounds__(224, 3) k_deconv2(const float* __restrict__ dw2,
                                                    const float* __restrict__ db2,
                                                    float* __restrict__ out_recon) {
    extern __shared__ float sm[];
    float* insm = sm;            // 2 x 32 x 16 x 17 = 17408
    float* ws = sm + 17408;      // 512
    int t = threadIdx.x, b0 = blockIdx.x * 2;
    for (int l = t; l < 512; l += 224) ws[l] = dw2[l];
    for (int l = t; l < 17408; l += 224) insm[l] = 0.f;
    __syncthreads();
    for (int l = t; l < 12544; l += 224) {
        int img = l / 6272, rem = l % 6272;
        int ci = rem / 196, pos = rem % 196;
        int iy = pos / 14, ix = pos % 14;
        insm[img * 8704 + ci * 272 + (iy + 1) * 17 + ix + 1] = g_d1[(b0 + img) * 6272 + rem];
    }
    __syncthreads();
    int img = t / 112, r2 = t % 112;
    int par = r2 / 28, rem2 = r2 % 28;
    int q = rem2 / 2, rh = rem2 % 2, r0c = rh * 7;
    int ay = par >> 1, ax = par & 1;
    float acc[7];
    float bv = db2[0];
    #pragma unroll
    for (int r = 0; r < 7; r++) acc[r] = bv;
    const float* inb = insm + img * 8704;
    #pragma unroll
    for (int dy = 0; dy < 2; dy++)
    #pragma unroll
    for (int dx = 0; dx < 2; dx++) {
        int ky = 2 * dy + ay, kx = 2 * dx + ax;
        const float* inr = inb + (q + dy + ay) * 17 + r0c + dx + ax;
        const float* wp = ws + (ky * 4 + kx) * 32;
        #pragma unroll 8
        for (int ci = 0; ci < 32; ci++) {
            float w = wp[ci];
            const float* ip = inr + ci * 272;
            #pragma unroll
            for (int r = 0; r < 7; r++) acc[r] += ip[r] * w;
        }
    }
    int oy = 2 * q + ay;
    float* ob = out_recon + (b0 + img) * 784 + oy * 28 + ax;
    #pragma unroll
    for (int r = 0; r < 7; r++) {
        float v = acc[r];
        ob[2 * (r0c + r)] = 1.f / (1.f + __expf(-v));
    }
}

// ---------------- launch ----------------
extern "C" void kernel_launch(void* const* d_in, const int* in_sizes, int n_in,
                              void* d_out, int out_size) {
    const float* x   = (const float*)d_in[0];
    const float* w1  = (const float*)d_in[1];
    const float* b1  = (const float*)d_in[2];
    const float* w2  = (const float*)d_in[3];
    const float* b2  = (const float*)d_in[4];
    const float* w3  = (const float*)d_in[5];
    const float* b3  = (const float*)d_in[6];
    const float* cb  = (const float*)d_in[7];
    const float* dw0 = (const float*)d_in[8];
    const float* db0 = (const float*)d_in[9];
    const float* dw1 = (const float*)d_in[10];
    const float* db1 = (const float*)d_in[11];
    const float* dw2 = (const float*)d_in[12];
    const float* db2 = (const float*)d_in[13];

    float* out = (float*)d_out;
    float* out_recon = out;                       // 4096*1*28*28 = 3,211,264
    float* out_z     = out_recon + 3211264;       // 12,845,056
    float* out_zq    = out_z + 12845056;          // 12,845,056
    float* out_vq    = out_zq + 12845056;         // 1
    float* out_idx   = out_vq + 1;                // 200,704

    cudaFuncSetAttribute(k_conv2,   cudaFuncAttributeMaxDynamicSharedMemorySize, C2_SMEM_WORDS * 4);
    cudaFuncSetAttribute(k_vq,      cudaFuncAttributeMaxDynamicSharedMemorySize, K3_SMEM_WORDS * 4);
    cudaFuncSetAttribute(k_deconv2, cudaFuncAttributeMaxDynamicSharedMemorySize, 71680);

    k_prep<<<129, 256>>>(cb, dw0, db0);
    k_conv1<<<4096, 256>>>(x, w1, b1);
    k_conv2<<<2048, 112, C2_SMEM_WORDS * 4>>>(w2, b2);
    k_vq<<<1568, 256, K3_SMEM_WORDS * 4>>>(w3, b3, cb, out_z, out_zq, out_idx);
    k_vqred<<<1, 256>>>(out_vq);
    k_deconv1<<<2048, 224>>>(dw1, db1);
    k_deconv2<<<2048, 224, 71680>>>(dw2, db2, out_recon);
}

// round 6
// speedup vs baseline: 2.6171x; 1.3415x over previous
#include <cuda_runtime.h>
#include <cuda_bf16.h>

typedef unsigned long long ull;

// ---------------- packed f32x2 helpers (FFMA2) ----------------
__device__ __forceinline__ ull f2pack(float lo, float hi) {
    ull d; asm("mov.b64 %0, {%1, %2};" : "=l"(d) : "f"(lo), "f"(hi)); return d;
}
__device__ __forceinline__ ull f2dup(float s) { return f2pack(s, s); }
__device__ __forceinline__ void f2unpack(float& lo, float& hi, ull s) {
    asm("mov.b64 {%0, %1}, %2;" : "=f"(lo), "=f"(hi) : "l"(s));
}
__device__ __forceinline__ ull f2fma(ull a, ull b, ull c) {
    ull d; asm("fma.rn.f32x2 %0, %1, %2, %3;" : "=l"(d) : "l"(a), "l"(b), "l"(c)); return d;
}

// ---------------- scratch (device globals; no allocation allowed) ----------------
__device__ float g_h1[4096 * 32 * 196];   // conv1 out (relu), NHWC [b][pos14x14][ci32]
__device__ float g_h2[4096 * 64 * 49];    // conv2 out (relu), row-major [m][co64]
__device__ int   g_idx[4096 * 49];        // VQ indices
__device__ float g_table[512 * 64];       // codebook @ dw0 + db0
__device__ float g_cbsq[512];             // ||codebook_c||^2 (XLA-order)
__device__ float g_vqpart[1568];          // per-block vq partial sums
__device__ float g_P[512 * 16 * 32];      // P[c][tap][co] = table[c] . dw1[tap][:][co]

// XLA GPU row-reduce order (matched reference in round 3).
__device__ __forceinline__ float xla_sumsq64(const float* v, int stride) {
    float p[64];
    #pragma unroll
    for (int k = 0; k < 64; k++) p[k] = __fmul_rn(v[k * stride], v[k * stride]);
    float a[32];
    #pragma unroll
    for (int i = 0; i < 32; i++) a[i] = __fadd_rn(p[i], p[i + 32]);
    #pragma unroll
    for (int s = 16; s > 0; s >>= 1)
        #pragma unroll
        for (int i = 0; i < 16; i++)
            if (i < s) a[i] = __fadd_rn(a[i], a[i + s]);
    return a[0];
}

// ---------------- K0: decode table + codebook norms ----------------
__global__ void k_prep(const float* __restrict__ cb, const float* __restrict__ dw0,
                       const float* __restrict__ db0) {
    int t = threadIdx.x;
    if (blockIdx.x < 128) {
        int id = blockIdx.x * 256 + t;
        int c = id >> 6, o = id & 63;
        float s = db0[o];
        const float* cr = cb + c * 64;
        #pragma unroll 8
        for (int i = 0; i < 64; i++) s += cr[i] * dw0[i * 64 + o];
        g_table[id] = s;
    } else {
        for (int c = t; c < 512; c += 256) g_cbsq[c] = xla_sumsq64(cb + c * 64, 1);
    }
}

// ---------------- K0b: P table (deconv1 folded through codebook) ----------------
__global__ void k_prep2(const float* __restrict__ dw1) {
    int id = blockIdx.x * 256 + threadIdx.x;   // 0..262143
    int co = id & 31, tap = (id >> 5) & 15, c = id >> 9;
    const float* tr = g_table + c * 64;
    const float* wr = dw1 + tap * 2048 + co;
    float s = 0.f;
    #pragma unroll 8
    for (int ci = 0; ci < 64; ci++) s += tr[ci] * wr[ci * 32];
    g_P[id] = s;
}

// ---------------- K1: conv1 4x4 s2 p1, 1->32, relu -> NHWC (FFMA2 co-pairs) ----------------
__global__ void __launch_bounds__(256) k_conv1(const float* __restrict__ x,
                                               const float* __restrict__ w1,
                                               const float* __restrict__ b1) {
    __shared__ float xs[900];
    __shared__ __align__(16) float ws[512];
    int b = blockIdx.x, t = threadIdx.x;
    for (int l = t; l < 900; l += 256) xs[l] = 0.f;
    for (int l = t; l < 512; l += 256) ws[l] = w1[l];
    __syncthreads();
    for (int l = t; l < 784; l += 256) {
        int iy = l / 28, ix = l % 28;
        xs[(iy + 1) * 30 + ix + 1] = x[b * 784 + l];
    }
    __syncthreads();
    if (t < 196) {
        int oy = t / 14, ox = t % 14;
        ull acc[16];
        const ulonglong2* b2p = (const ulonglong2*)b1;
        #pragma unroll
        for (int u = 0; u < 8; u++) {
            ulonglong2 bb = b2p[u];
            acc[2 * u] = bb.x; acc[2 * u + 1] = bb.y;
        }
        const ulonglong2* ws2 = (const ulonglong2*)ws;
        #pragma unroll
        for (int ky = 0; ky < 4; ky++)
        #pragma unroll
        for (int kx = 0; kx < 4; kx++) {
            float v = xs[(2 * oy + ky) * 30 + 2 * ox + kx];
            ull vp = f2dup(v);
            int tb = (ky * 4 + kx) * 8;
            #pragma unroll
            for (int u = 0; u < 8; u++) {
                ulonglong2 wv = ws2[tb + u];
                acc[2 * u] = f2fma(vp, wv.x, acc[2 * u]);
                acc[2 * u + 1] = f2fma(vp, wv.y, acc[2 * u + 1]);
            }
        }
        float4* o = (float4*)(g_h1 + b * 6272 + t * 32);
        #pragma unroll
        for (int u = 0; u < 8; u++) {
            float a0, a1, a2, a3;
            f2unpack(a0, a1, acc[2 * u]);
            f2unpack(a2, a3, acc[2 * u + 1]);
            float4 v4;
            v4.x = fmaxf(a0, 0.f); v4.y = fmaxf(a1, 0.f);
            v4.z = fmaxf(a2, 0.f); v4.w = fmaxf(a3, 0.f);
            o[u] = v4;
        }
    }
}

// ---------------- K2: conv2 4x4 s2 p1, 32->64, relu (img-pair FFMA2) ----------------
#define C2_CI_PAIR 546
#define C2_SMEM_WORDS (32 * C2_CI_PAIR)   // 17472 words = 69.9KB

__global__ void __launch_bounds__(112, 3) k_conv2(const float* __restrict__ w2,
                                                  const float* __restrict__ b2) {
    extern __shared__ __align__(16) float insm[];
    int t = threadIdx.x;
    int b0 = blockIdx.x * 2;
    for (int l = t; l < C2_SMEM_WORDS; l += 112) insm[l] = 0.f;
    __syncthreads();
    for (int l = t; l < 12544; l += 112) {
        int img = l & 1, ci = (l >> 1) & 31, pos = l >> 6;
        int iy = pos / 14, ix = pos % 14;
        insm[ci * C2_CI_PAIR + ((iy + 1) * 17 + ix + 1) * 2 + img] =
            g_h1[(b0 + img) * 6272 + pos * 32 + ci];
    }
    __syncthreads();
    int oy = t / 16, cog = t % 16, co0 = cog * 4;
    ull acc[7][4];
    {
        float4 bf = ((const float4*)b2)[cog];
        ull bd0 = f2dup(bf.x), bd1 = f2dup(bf.y), bd2 = f2dup(bf.z), bd3 = f2dup(bf.w);
        #pragma unroll
        for (int i = 0; i < 7; i++) {
            acc[i][0] = bd0; acc[i][1] = bd1; acc[i][2] = bd2; acc[i][3] = bd3;
        }
    }
    const float4* w24 = (const float4*)w2;
    const ull* insm2 = (const ull*)insm;
    for (int tap = 0; tap < 16; tap++) {
        int ky = tap >> 2, kx = tap & 3;
        int base = (2 * oy + ky) * 17 + kx;
        int wb = tap * 512 + cog;
        #pragma unroll 8
        for (int ci = 0; ci < 32; ci++) {
            float4 w4 = __ldg(&w24[wb + ci * 16]);
            ull wd0 = f2dup(w4.x), wd1 = f2dup(w4.y), wd2 = f2dup(w4.z), wd3 = f2dup(w4.w);
            const ull* ip = insm2 + ci * 273 + base;
            #pragma unroll
            for (int ox = 0; ox < 7; ox++) {
                ull v = ip[2 * ox];
                acc[ox][0] = f2fma(v, wd0, acc[ox][0]);
                acc[ox][1] = f2fma(v, wd1, acc[ox][1]);
                acc[ox][2] = f2fma(v, wd2, acc[ox][2]);
                acc[ox][3] = f2fma(v, wd3, acc[ox][3]);
            }
        }
    }
    size_t mA = (size_t)b0 * 49 + oy * 7;
    #pragma unroll
    for (int ox = 0; ox < 7; ox++) {
        float4 vA, vB;
        float lo, hi;
        f2unpack(lo, hi, acc[ox][0]); vA.x = fmaxf(lo, 0.f); vB.x = fmaxf(hi, 0.f);
        f2unpack(lo, hi, acc[ox][1]); vA.y = fmaxf(lo, 0.f); vB.y = fmaxf(hi, 0.f);
        f2unpack(lo, hi, acc[ox][2]); vA.z = fmaxf(lo, 0.f); vB.z = fmaxf(hi, 0.f);
        f2unpack(lo, hi, acc[ox][3]); vA.w = fmaxf(lo, 0.f); vB.w = fmaxf(hi, 0.f);
        *(float4*)(g_h2 + (mA + ox) * 64 + co0) = vA;
        *(float4*)(g_h2 + (mA + 49 + ox) * 64 + co0) = vB;
    }
}

// ---------------- K3: conv3 (1x1, 64->64) + VQ, fused (FFMA2) -- UNCHANGED ----------------
#define HS_OFF    0
#define WSM_OFF   8704
#define ZSM_OFF   12800
#define CBSQ_OFF  21120
#define ROWB_OFF  21248
#define ROWP_OFF  21376
#define WIDX_OFF  21504
#define SRED_OFF  21632
#define ZSQ_OFF   21888
#define K3_SMEM_WORDS 22016

__global__ void __launch_bounds__(256, 2) k_vq(const float* __restrict__ w3,
                                               const float* __restrict__ b3,
                                               const float* __restrict__ cb,
                                               float* __restrict__ out_z,
                                               float* __restrict__ out_zq,
                                               float* __restrict__ out_idx) {
    extern __shared__ __align__(16) float sm[];
    float* hs = sm + HS_OFF;
    float* wsm = sm + WSM_OFF;
    float* zsm = sm + ZSM_OFF;          // col-major [k][r], stride 130
    float* rs = sm + WSM_OFF;           // overlays wsm (dead after GEMM1)
    int* ri = (int*)(sm + WSM_OFF + 2048);
    float* cbsqs = sm + CBSQ_OFF;
    int* rowb = (int*)(sm + ROWB_OFF);
    int* rowp = (int*)(sm + ROWP_OFF);
    int* widx = (int*)(sm + WIDX_OFF);
    float* sred = sm + SRED_OFF;
    float* zsq_s = sm + ZSQ_OFF;

    int t = threadIdx.x;
    int m0 = blockIdx.x * 128;
    if (t < 128) { int m = m0 + t; rowb[t] = m / 49; rowp[t] = m % 49; }
    for (int l = t; l < 4096; l += 256) wsm[l] = w3[l];
    for (int l = t; l < 8192; l += 256) {
        int r = l >> 6, ci = l & 63;
        hs[r * 68 + ci] = g_h2[(size_t)(m0 + r) * 64 + ci];
    }
    __syncthreads();
    {
        int rg = t >> 4, cg = t & 15;
        int r0 = rg * 8, co0 = cg * 4;
        ull acc[8][2];
        {
            ulonglong2 bb = ((const ulonglong2*)b3)[cg];
            #pragma unroll
            for (int j = 0; j < 8; j++) { acc[j][0] = bb.x; acc[j][1] = bb.y; }
        }
        const ulonglong2* wsm2 = (const ulonglong2*)wsm;
        #pragma unroll 4
        for (int ci = 0; ci < 64; ci++) {
            ulonglong2 wv = wsm2[ci * 16 + cg];
            #pragma unroll
            for (int j = 0; j < 8; j++) {
                ull ap = f2dup(hs[(r0 + j) * 68 + ci]);
                acc[j][0] = f2fma(ap, wv.x, acc[j][0]);
                acc[j][1] = f2fma(ap, wv.y, acc[j][1]);
            }
        }
        #pragma unroll
        for (int j = 0; j < 8; j++) {
            float z0, z1, z2, z3;
            f2unpack(z0, z1, acc[j][0]);
            f2unpack(z2, z3, acc[j][1]);
            int r = r0 + j;
            zsm[(co0 + 0) * 130 + r] = z0;
            zsm[(co0 + 1) * 130 + r] = z1;
            zsm[(co0 + 2) * 130 + r] = z2;
            zsm[(co0 + 3) * 130 + r] = z3;
        }
    }
    __syncthreads();
    if (t < 128) zsq_s[t] = xla_sumsq64(zsm + t, 130);
    for (int l = t; l < 8192; l += 256) {
        int r = l & 127, co = l >> 7;
        out_z[rowb[r] * 3136 + co * 49 + rowp[r]] = zsm[co * 130 + r];
    }
    float bsv[8]; int bix[8];
    #pragma unroll
    for (int j = 0; j < 8; j++) { bsv[j] = 3.4e38f; bix[j] = 0; }
    int rg = t >> 4, cg2 = t & 15;
    int r0 = rg * 8, c0 = cg2 * 8;
    float4* cs4 = (float4*)hs;
    const float2* cs2 = (const float2*)hs;
    const ull* zz = (const ull*)zsm;
    for (int cc = 0; cc < 4; cc++) {
        __syncthreads();
        {
            const float4* cb4 = (const float4*)(cb) + cc * 2048;
            for (int l = t; l < 2048; l += 256) {
                int c = l >> 4, d4 = l & 15;
                cs4[c * 16 + ((d4 + (c >> 3)) & 15)] = cb4[l];
            }
        }
        if (t < 128) cbsqs[t] = g_cbsq[cc * 128 + t];
        __syncthreads();
        ull acc[4][8];
        #pragma unroll
        for (int p = 0; p < 4; p++)
            #pragma unroll
            for (int jc = 0; jc < 8; jc++) acc[p][jc] = 0ull;
        for (int d4 = 0; d4 < 16; d4++) {
            ull zpa[2][4];
            #pragma unroll
            for (int kk = 0; kk < 2; kk++) {
                int base = (4 * d4 + kk) * 65 + rg * 4;
                #pragma unroll
                for (int p = 0; p < 4; p++) zpa[kk][p] = zz[base + p];
            }
            #pragma unroll
            for (int jc = 0; jc < 8; jc++) {
                float2 cv = cs2[((c0 + jc) * 16 + ((d4 + cg2) & 15)) * 2];
                ull cd0 = f2dup(cv.x), cd1 = f2dup(cv.y);
                #pragma unroll
                for (int p = 0; p < 4; p++) {
                    ull a = acc[p][jc];
                    a = f2fma(zpa[0][p], cd0, a);
                    a = f2fma(zpa[1][p], cd1, a);
                    acc[p][jc] = a;
                }
            }
            #pragma unroll
            for (int kk = 0; kk < 2; kk++) {
                int base = (4 * d4 + 2 + kk) * 65 + rg * 4;
                #pragma unroll
                for (int p = 0; p < 4; p++) zpa[kk][p] = zz[base + p];
            }
            #pragma unroll
            for (int jc = 0; jc < 8; jc++) {
                float2 cv = cs2[((c0 + jc) * 16 + ((d4 + cg2) & 15)) * 2 + 1];
                ull cd2 = f2dup(cv.x), cd3 = f2dup(cv.y);
                #pragma unroll
                for (int p = 0; p < 4; p++) {
                    ull a = acc[p][jc];
                    a = f2fma(zpa[0][p], cd2, a);
                    a = f2fma(zpa[1][p], cd3, a);
                    acc[p][jc] = a;
                }
            }
        }
        #pragma unroll
        for (int jc = 0; jc < 8; jc++) {
            float qn = cbsqs[c0 + jc];
            int id = cc * 128 + c0 + jc;
            #pragma unroll
            for (int p = 0; p < 4; p++) {
                float d0, d1;
                f2unpack(d0, d1, acc[p][jc]);
                {
                    float T = __fadd_rn(zsq_s[r0 + 2 * p], qn);
                    float d = __fadd_rn(T, -__fmul_rn(2.0f, d0));
                    if (d < bsv[2 * p]) { bsv[2 * p] = d; bix[2 * p] = id; }
                }
                {
                    float T = __fadd_rn(zsq_s[r0 + 2 * p + 1], qn);
                    float d = __fadd_rn(T, -__fmul_rn(2.0f, d1));
                    if (d < bsv[2 * p + 1]) { bsv[2 * p + 1] = d; bix[2 * p + 1] = id; }
                }
            }
        }
    }
    __syncthreads();
    #pragma unroll
    for (int j = 0; j < 8; j++) { rs[(r0 + j) * 16 + cg2] = bsv[j]; ri[(r0 + j) * 16 + cg2] = bix[j]; }
    __syncthreads();
    if (t < 128) {
        float best = rs[t * 16]; int bid = ri[t * 16];
        #pragma unroll
        for (int k = 1; k < 16; k++) {
            float s = rs[t * 16 + k]; int id = ri[t * 16 + k];
            if (s < best || (s == best && id < bid)) { best = s; bid = id; }
        }
        widx[t] = bid;
        int m = m0 + t;
        g_idx[m] = bid;
        out_idx[m] = (float)bid;
    }
    __syncthreads();
    float psum = 0.f;
    for (int l = t; l < 8192; l += 256) {
        int r = l & 127, co = l >> 7;
        float q = cb[widx[r] * 64 + co];
        float zv = zsm[co * 130 + r];
        float st = __fadd_rn(zv, __fadd_rn(q, -zv));
        out_zq[rowb[r] * 3136 + co * 49 + rowp[r]] = st;
        float d = zv - q;
        psum += d * d;
    }
    sred[t] = psum;
    __syncthreads();
    for (int s = 128; s > 0; s >>= 1) {
        if (t < s) sred[t] += sred[t + s];
        __syncthreads();
    }
    if (t == 0) g_vqpart[blockIdx.x] = sred[0];
}

// ---------------- K3b: vq loss final reduce ----------------
__global__ void k_vqred(float* __restrict__ out_vq) {
    __shared__ float sred[256];
    int t = threadIdx.x;
    float s = 0.f;
    for (int l = t; l < 1568; l += 256) s += g_vqpart[l];
    sred[t] = s;
    __syncthreads();
    for (int k = 128; k > 0; k >>= 1) { if (t < k) sred[t] += sred[t + k]; __syncthreads(); }
    if (t == 0) out_vq[0] = sred[0] * 1.25f / (200704.f * 64.f);
}

// ---------------- K4: fused deconv1(P-table) + relu + deconv2 + sigmoid ----------------
// Phase 1: d1[co][14x14] = relu(db1 + sum of <=4 P rows) into smem.
// Phase 2: recon = sigmoid(deconv2(d1)), parity mapping identical to verified K5.
__global__ void __launch_bounds__(256) k_dec(const float* __restrict__ db1,
                                             const float* __restrict__ dw2,
                                             const float* __restrict__ db2,
                                             float* __restrict__ out_recon) {
    __shared__ float d1s[32 * 273];   // [ci][16x17 padded, stride 273]
    __shared__ float ws[512];
    __shared__ int sidx[49];
    int t = threadIdx.x, b = blockIdx.x;
    if (t < 49) sidx[t] = g_idx[b * 49 + t];
    for (int l = t; l < 512; l += 256) ws[l] = dw2[l];
    for (int l = t; l < 32 * 273; l += 256) d1s[l] = 0.f;
    __syncthreads();
    // phase 1: 1568 tasks = 8 co-quads x 196 positions (g-major: warp stores conflict-free)
    const float4* P4 = (const float4*)g_P;
    const float4* db14 = (const float4*)db1;
    for (int l = t; l < 1568; l += 256) {
        int g = l / 196, pos = l % 196;
        int oy = pos / 14, ox = pos % 14;
        float4 a = __ldg(&db14[g]);
        int kyb = oy & 1, kxb = ox & 1;
        #pragma unroll
        for (int dy = 0; dy < 2; dy++) {
            int ky = kyb + 2 * dy;
            int i = (oy + ky - 2) >> 1;
            if ((unsigned)i < 7u) {
                #pragma unroll
                for (int dx = 0; dx < 2; dx++) {
                    int kx = kxb + 2 * dx;
                    int j = (ox + kx - 2) >> 1;
                    if ((unsigned)j < 7u) {
                        int c = sidx[i * 7 + j];
                        float4 p = __ldg(&P4[(c * 16 + ky * 4 + kx) * 8 + g]);
                        a.x += p.x; a.y += p.y; a.z += p.z; a.w += p.w;
                    }
                }
            }
        }
        int sp = (oy + 1) * 17 + ox + 1;
        d1s[(4 * g + 0) * 273 + sp] = fmaxf(a.x, 0.f);
        d1s[(4 * g + 1) * 273 + sp] = fmaxf(a.y, 0.f);
        d1s[(4 * g + 2) * 273 + sp] = fmaxf(a.z, 0.f);
        d1s[(4 * g + 3) * 273 + sp] = fmaxf(a.w, 0.f);
    }
    __syncthreads();
    // phase 2: deconv2 4x4 up2 p2 (32->1) + sigmoid; 112 threads
    if (t < 112) {
        int par = t / 28, rem2 = t % 28;
        int q = rem2 >> 1, rh = rem2 & 1, r0c = rh * 7;
        int ay = par >> 1, ax = par & 1;
        float acc[7];
        float bv = db2[0];
        #pragma unroll
        for (int r = 0; r < 7; r++) acc[r] = bv;
        #pragma unroll
        for (int dy = 0; dy < 2; dy++)
        #pragma unroll
        for (int dx = 0; dx < 2; dx++) {
            int ky = 2 * dy + ay, kx = 2 * dx + ax;
            const float* inr = d1s + (q + dy + ay) * 17 + r0c + dx + ax;
            const float* wp = ws + (ky * 4 + kx) * 32;
            #pragma unroll 8
            for (int ci = 0; ci < 32; ci++) {
                float w = wp[ci];
                const float* ip = inr + ci * 273;
                #pragma unroll
                for (int r = 0; r < 7; r++) acc[r] += ip[r] * w;
            }
        }
        int oy = 2 * q + ay;
        float* ob = out_recon + b * 784 + oy * 28 + ax;
        #pragma unroll
        for (int r = 0; r < 7; r++) {
            float v = acc[r];
            ob[2 * (r0c + r)] = 1.f / (1.f + __expf(-v));
        }
    }
}

// ---------------- launch ----------------
extern "C" void kernel_launch(void* const* d_in, const int* in_sizes, int n_in,
                              void* d_out, int out_size) {
    const float* x   = (const float*)d_in[0];
    const float* w1  = (const float*)d_in[1];
    const float* b1  = (const float*)d_in[2];
    const float* w2  = (const float*)d_in[3];
    const float* b2  = (const float*)d_in[4];
    const float* w3  = (const float*)d_in[5];
    const float* b3  = (const float*)d_in[6];
    const float* cb  = (const float*)d_in[7];
    const float* dw0 = (const float*)d_in[8];
    const float* db0 = (const float*)d_in[9];
    const float* dw1 = (const float*)d_in[10];
    const float* db1 = (const float*)d_in[11];
    const float* dw2 = (const float*)d_in[12];
    const float* db2 = (const float*)d_in[13];

    float* out = (float*)d_out;
    float* out_recon = out;                       // 3,211,264
    float* out_z     = out_recon + 3211264;       // 12,845,056
    float* out_zq    = out_z + 12845056;          // 12,845,056
    float* out_vq    = out_zq + 12845056;         // 1
    float* out_idx   = out_vq + 1;                // 200,704

    cudaFuncSetAttribute(k_conv2, cudaFuncAttributeMaxDynamicSharedMemorySize, C2_SMEM_WORDS * 4);
    cudaFuncSetAttribute(k_vq,    cudaFuncAttributeMaxDynamicSharedMemorySize, K3_SMEM_WORDS * 4);

    k_prep<<<129, 256>>>(cb, dw0, db0);
    k_prep2<<<1024, 256>>>(dw1);
    k_conv1<<<4096, 256>>>(x, w1, b1);
    k_conv2<<<2048, 112, C2_SMEM_WORDS * 4>>>(w2, b2);
    k_vq<<<1568, 256, K3_SMEM_WORDS * 4>>>(w3, b3, cb, out_z, out_zq, out_idx);
    k_vqred<<<1, 256>>>(out_vq);
    k_dec<<<4096, 256>>>(db1, dw2, db2, out_recon);
}